// round 1
// baseline (speedup 1.0000x reference)
#include <cuda_runtime.h>

#define A_N 100000
#define B_N 200000
#define M_N 50000
#define H_N 128
#define NMOL_N 4000
#define MAXNB 8
#define FA 35
#define FB 40

// Scratch (device globals — no allocations allowed)
__device__ __align__(128) float g_gm0[(size_t)B_N * H_N];     // graph_message buf A (102 MB)
__device__ __align__(128) float g_gm1[(size_t)B_N * H_N];     // graph_message buf B (102 MB)
__device__ __align__(128) float g_binput[(size_t)B_N * H_N];  // pre-relu bond input (102 MB)
__device__ __align__(128) float g_ah[(size_t)A_N * H_N];      // atom hiddens (51 MB)

// ---------------------------------------------------------------------------
// Register-blocked tile GEMM: 32 rows x 128 cols, K-chunk of NSTEPS*4 columns.
// Thread map: tx = t&31 -> 4 consecutive h (tx*4..), wy = t>>5 -> rows wy*4..wy*4+3.
// sW: [64][128] row-major (k, h). sX: [32][64] row-major (row, k).
// X smem loads are warp-uniform (broadcast); W loads are 512B contiguous per warp.
// ---------------------------------------------------------------------------
template <int NSTEPS>
__device__ __forceinline__ void gemm_tile(const float* sW, const float* sX,
                                          int r0, int tx, float4 acc[4]) {
    const float4* w4 = (const float4*)sW;
    const float4* x4 = (const float4*)sX;
#pragma unroll
    for (int k4 = 0; k4 < NSTEPS; k4++) {
        float4 xv[4];
        float4 wv[4];
#pragma unroll
        for (int r = 0; r < 4; r++) xv[r] = x4[(r0 + r) * 16 + k4];
#pragma unroll
        for (int kk = 0; kk < 4; kk++) wv[kk] = w4[(k4 * 4 + kk) * 32 + tx];
#pragma unroll
        for (int r = 0; r < 4; r++) {
            const float* xp = (const float*)&xv[r];
#pragma unroll
            for (int kk = 0; kk < 4; kk++) {
                acc[r].x = fmaf(xp[kk], wv[kk].x, acc[r].x);
                acc[r].y = fmaf(xp[kk], wv[kk].y, acc[r].y);
                acc[r].z = fmaf(xp[kk], wv[kk].z, acc[r].z);
                acc[r].w = fmaf(xp[kk], wv[kk].w, acc[r].w);
            }
        }
    }
}

// Gather-sum of 8 neighbor message rows (cols k0..k0+63) into sX for 32 rows.
// message = concat(tree [M,H], graph [B,H]) realized via branchless pointer select.
// Each warp fills 4 rows; lane handles 2 consecutive floats (256B/warp per gather).
__device__ __forceinline__ void gather_fill(float* sX, const int* __restrict__ graph,
                                            const float* __restrict__ tree,
                                            const float* __restrict__ src,
                                            int base, int k0, int wy, int lane) {
#pragma unroll
    for (int rr = 0; rr < 4; rr++) {
        int r = wy + rr * 8;
        int row = base + r;
        float sx = 0.f, sy = 0.f;
#pragma unroll
        for (int j = 0; j < MAXNB; j++) {
            int idx = graph[row * MAXNB + j];
            const float* p = (idx < M_N) ? (tree + (size_t)idx * H_N)
                                         : (src + (size_t)(idx - M_N) * H_N);
            float2 v = *(const float2*)(p + k0 + lane * 2);
            sx += v.x;
            sy += v.y;
        }
        *(float2*)(sX + r * 64 + lane * 2) = make_float2(sx, sy);
    }
}

// ---------------------------------------------------------------------------
// binput = fbonds @ W_i ; g_gm0 = relu(binput)
// ---------------------------------------------------------------------------
__global__ __launch_bounds__(256) void k_binput(const float* __restrict__ fbonds,
                                                const float* __restrict__ Wi) {
    __shared__ __align__(16) float sW[FB * H_N];  // 20 KB
    __shared__ __align__(16) float sF[32 * FB];   // 5 KB
    int t = threadIdx.x;
    int tx = t & 31, wy = t >> 5;
    int b0 = blockIdx.x * 32;
    {
        const float4* src = (const float4*)Wi;
        float4* dst = (float4*)sW;
        for (int i = t; i < FB * H_N / 4; i += 256) dst[i] = src[i];
    }
    {
        const float4* src = (const float4*)(fbonds + (size_t)b0 * FB);
        float4* dst = (float4*)sF;
        for (int i = t; i < 32 * FB / 4; i += 256) dst[i] = src[i];
    }
    __syncthreads();
    int r0 = wy * 4;
    float4 acc[4];
#pragma unroll
    for (int r = 0; r < 4; r++) acc[r] = make_float4(0.f, 0.f, 0.f, 0.f);
    const float4* w4 = (const float4*)sW;
#pragma unroll
    for (int k = 0; k < FB; k++) {
        float4 w = w4[k * 32 + tx];
#pragma unroll
        for (int r = 0; r < 4; r++) {
            float x = sF[(r0 + r) * FB + k];
            acc[r].x = fmaf(x, w.x, acc[r].x);
            acc[r].y = fmaf(x, w.y, acc[r].y);
            acc[r].z = fmaf(x, w.z, acc[r].z);
            acc[r].w = fmaf(x, w.w, acc[r].w);
        }
    }
#pragma unroll
    for (int r = 0; r < 4; r++) {
        size_t b = (size_t)(b0 + r0 + r);
        ((float4*)g_binput)[b * 32 + tx] = acc[r];
        float4 o = make_float4(fmaxf(acc[r].x, 0.f), fmaxf(acc[r].y, 0.f),
                               fmaxf(acc[r].z, 0.f), fmaxf(acc[r].w, 0.f));
        ((float4*)g_gm0)[b * 32 + tx] = o;
    }
}

// ---------------------------------------------------------------------------
// One message-passing iteration:
//   dst = relu(binput + (gather_sum(src via bgraph)) @ W_h)
// srcsel==0: src=g_gm0, dst=g_gm1 ; srcsel==1: src=g_gm1, dst=g_gm0.
// ---------------------------------------------------------------------------
__global__ __launch_bounds__(256) void k_iter(const float* __restrict__ tree,
                                              const int* __restrict__ bgraph,
                                              const float* __restrict__ Wh,
                                              int srcsel) {
    __shared__ __align__(16) float sW[64 * H_N];  // 32 KB
    __shared__ __align__(16) float sX[32 * 64];   // 8 KB
    const float* src = srcsel ? g_gm1 : g_gm0;
    float* dst = srcsel ? g_gm0 : g_gm1;
    int t = threadIdx.x;
    int tx = t & 31, wy = t >> 5;
    int b0 = blockIdx.x * 32;
    float4 acc[4];
#pragma unroll
    for (int r = 0; r < 4; r++) acc[r] = make_float4(0.f, 0.f, 0.f, 0.f);

#pragma unroll
    for (int c = 0; c < 2; c++) {
        int k0 = c * 64;
        if (c) __syncthreads();  // protect smem reuse between chunks
        {
            const float4* wsrc = (const float4*)(Wh + (size_t)k0 * H_N);
            float4* wdst = (float4*)sW;
#pragma unroll
            for (int i = 0; i < 8; i++) wdst[t + i * 256] = wsrc[t + i * 256];
        }
        gather_fill(sX, bgraph, tree, src, b0, k0, wy, tx);
        __syncthreads();
        gemm_tile<16>(sW, sX, wy * 4, tx, acc);
    }
    int r0 = wy * 4;
#pragma unroll
    for (int r = 0; r < 4; r++) {
        size_t b = (size_t)(b0 + r0 + r);
        float4 bi = ((const float4*)g_binput)[b * 32 + tx];
        float4 o = make_float4(fmaxf(acc[r].x + bi.x, 0.f), fmaxf(acc[r].y + bi.y, 0.f),
                               fmaxf(acc[r].z + bi.z, 0.f), fmaxf(acc[r].w + bi.w, 0.f));
        ((float4*)dst)[b * 32 + tx] = o;
    }
}

// ---------------------------------------------------------------------------
// Atom stage: ah = relu([fatoms, gather_sum(final msg via agraph)] @ W_o + b_o)
// K split: chunk0 = fatoms (35 cols, zero-padded to 36), chunks 1-2 = nei (2x64).
// Final message graph part lives in g_gm0 (after 4 iterations).
// ---------------------------------------------------------------------------
__global__ __launch_bounds__(256) void k_atom(const float* __restrict__ fatoms,
                                              const float* __restrict__ tree,
                                              const int* __restrict__ agraph,
                                              const float* __restrict__ Wo,
                                              const float* __restrict__ bo) {
    __shared__ __align__(16) float sW[64 * H_N];
    __shared__ __align__(16) float sX[32 * 64];
    int t = threadIdx.x;
    int tx = t & 31, wy = t >> 5;
    int a0 = blockIdx.x * 32;
    float4 bov = ((const float4*)bo)[tx];
    float4 acc[4];
#pragma unroll
    for (int r = 0; r < 4; r++) acc[r] = bov;  // bias folded into accumulator

    // chunk 0: fatoms columns (35 real + 1 zero pad -> 36)
    {
        const float4* wsrc = (const float4*)Wo;
        float4* wdst = (float4*)sW;
        for (int i = t; i < FA * H_N / 4; i += 256) wdst[i] = wsrc[i];  // rows 0..34
        if (t < H_N) sW[FA * H_N + t] = 0.f;                            // zero row 35
        for (int i = t; i < 32 * FA; i += 256) {
            int r = i / FA;
            sX[r * 64 + (i - r * FA)] = fatoms[(size_t)a0 * FA + i];
        }
        if (t < 32) sX[t * 64 + FA] = 0.f;  // zero pad col
        __syncthreads();
        gemm_tile<9>(sW, sX, wy * 4, tx, acc);
    }
    // chunks 1-2: gathered neighbor message columns
#pragma unroll
    for (int c = 0; c < 2; c++) {
        int k0 = c * 64;
        __syncthreads();
        {
            const float4* wsrc = (const float4*)(Wo + (size_t)(FA + k0) * H_N);
            float4* wdst = (float4*)sW;
#pragma unroll
            for (int i = 0; i < 8; i++) wdst[t + i * 256] = wsrc[t + i * 256];
        }
        gather_fill(sX, agraph, tree, g_gm0, a0, k0, wy, tx);
        __syncthreads();
        gemm_tile<16>(sW, sX, wy * 4, tx, acc);
    }
    int r0 = wy * 4;
#pragma unroll
    for (int r = 0; r < 4; r++) {
        size_t a = (size_t)(a0 + r0 + r);
        float4 o = make_float4(fmaxf(acc[r].x, 0.f), fmaxf(acc[r].y, 0.f),
                               fmaxf(acc[r].z, 0.f), fmaxf(acc[r].w, 0.f));
        ((float4*)g_ah)[a * 32 + tx] = o;
    }
}

// ---------------------------------------------------------------------------
// Segment mean: mol_id is sorted, so block m binary-searches its [lo,hi) range.
// Fully deterministic (no fp32 atomics).
// ---------------------------------------------------------------------------
__global__ __launch_bounds__(128) void k_mol(const int* __restrict__ mol_id,
                                             float* __restrict__ out) {
    int m = blockIdx.x;
    int h = threadIdx.x;
    __shared__ int sb[2];
    if (h < 2) {
        int v = m + h;
        int lo = 0, hi = A_N;
        while (lo < hi) {
            int mid = (lo + hi) >> 1;
            if (mol_id[mid] < v) lo = mid + 1;
            else hi = mid;
        }
        sb[h] = lo;
    }
    __syncthreads();
    int lo = sb[0], hi = sb[1];
    float s = 0.f;
    for (int a = lo; a < hi; a++) s += g_ah[(size_t)a * H_N + h];
    out[(size_t)m * H_N + h] = s / fmaxf((float)(hi - lo), 1.f);
}

// ---------------------------------------------------------------------------
extern "C" void kernel_launch(void* const* d_in, const int* in_sizes, int n_in,
                              void* d_out, int out_size) {
    const float* fatoms = (const float*)d_in[0];
    const float* fbonds = (const float*)d_in[1];
    const float* tree   = (const float*)d_in[2];
    const int*   agraph = (const int*)d_in[3];
    const int*   bgraph = (const int*)d_in[4];
    const int*   mol_id = (const int*)d_in[5];
    const float* Wi     = (const float*)d_in[6];
    const float* Wh     = (const float*)d_in[7];
    const float* Wo     = (const float*)d_in[8];
    const float* bo     = (const float*)d_in[9];
    float* out = (float*)d_out;

    k_binput<<<B_N / 32, 256>>>(fbonds, Wi);
    // DEPTH-1 = 4 message-passing iterations, ping-pong gm0 <-> gm1
    k_iter<<<B_N / 32, 256>>>(tree, bgraph, Wh, 0);  // gm0 -> gm1
    k_iter<<<B_N / 32, 256>>>(tree, bgraph, Wh, 1);  // gm1 -> gm0
    k_iter<<<B_N / 32, 256>>>(tree, bgraph, Wh, 0);  // gm0 -> gm1
    k_iter<<<B_N / 32, 256>>>(tree, bgraph, Wh, 1);  // gm1 -> gm0  (final in gm0)
    k_atom<<<A_N / 32, 256>>>(fatoms, tree, agraph, Wo, bo);
    k_mol<<<NMOL_N, 128>>>(mol_id, out);
}

// round 2
// speedup vs baseline: 1.3157x; 1.3157x over previous
#include <cuda_runtime.h>

#define A_N 100000
#define B_N 200000
#define M_N 50000
#define H_N 128
#define NMOL_N 4000
#define MAXNB 8
#define FA 35
#define FB 40

// Scratch (device globals — no allocations allowed)
__device__ __align__(128) float g_gm0[(size_t)B_N * H_N];
__device__ __align__(128) float g_gm1[(size_t)B_N * H_N];
__device__ __align__(128) float g_binput[(size_t)B_N * H_N];
__device__ __align__(128) float g_ah[(size_t)A_N * H_N];

// ---------------------------------------------------------------------------
// 64-row x 128-col tile GEMM, 8 rows x 4 cols per thread.
// tx = t&31 -> h columns tx*4..tx*4+3 ; wy = t>>5 -> rows {wy, wy+8, ..., wy+56}.
// sW: [NSTEPS*4][128] row-major (k, h). sX: rows of XS4 float4 each (row, k).
// xv loads are warp-broadcast (whole warp shares wy); wv loads are 512B
// contiguous per warp -> conflict-free. 12 LDS.128 per 128 FMAs (1.5 B/FMA).
// ---------------------------------------------------------------------------
template <int NSTEPS, int XS4>
__device__ __forceinline__ void gemm_tile64(const float* sW, const float* sX,
                                            int wy, int tx, float4 acc[8]) {
    const float4* w4 = (const float4*)sW;
    const float4* x4 = (const float4*)sX;
#pragma unroll
    for (int k4 = 0; k4 < NSTEPS; k4++) {
        float4 wv[4];
#pragma unroll
        for (int kk = 0; kk < 4; kk++) wv[kk] = w4[(k4 * 4 + kk) * 32 + tx];
#pragma unroll
        for (int rr = 0; rr < 8; rr++) {
            float4 xv = x4[(wy + rr * 8) * XS4 + k4];
            acc[rr].x = fmaf(xv.x, wv[0].x, acc[rr].x);
            acc[rr].y = fmaf(xv.x, wv[0].y, acc[rr].y);
            acc[rr].z = fmaf(xv.x, wv[0].z, acc[rr].z);
            acc[rr].w = fmaf(xv.x, wv[0].w, acc[rr].w);
            acc[rr].x = fmaf(xv.y, wv[1].x, acc[rr].x);
            acc[rr].y = fmaf(xv.y, wv[1].y, acc[rr].y);
            acc[rr].z = fmaf(xv.y, wv[1].z, acc[rr].z);
            acc[rr].w = fmaf(xv.y, wv[1].w, acc[rr].w);
            acc[rr].x = fmaf(xv.z, wv[2].x, acc[rr].x);
            acc[rr].y = fmaf(xv.z, wv[2].y, acc[rr].y);
            acc[rr].z = fmaf(xv.z, wv[2].z, acc[rr].z);
            acc[rr].w = fmaf(xv.z, wv[2].w, acc[rr].w);
            acc[rr].x = fmaf(xv.w, wv[3].x, acc[rr].x);
            acc[rr].y = fmaf(xv.w, wv[3].y, acc[rr].y);
            acc[rr].z = fmaf(xv.w, wv[3].z, acc[rr].z);
            acc[rr].w = fmaf(xv.w, wv[3].w, acc[rr].w);
        }
    }
}

// ---------------------------------------------------------------------------
// Gather-sum of 8 neighbor rows (cols k0..k0+63) into sX[64][64] for 64 rows.
// 4 threads per row; each accumulates 16 consecutive cols in registers.
// bgraph reads coalesce to one 32B sector per row within a warp.
// ---------------------------------------------------------------------------
__device__ __forceinline__ void gather64(float* sX, const int* __restrict__ graph,
                                         const float* __restrict__ tree,
                                         const float* __restrict__ src,
                                         int base, int k0, int t, int nvalid) {
    int row = t >> 2;
    int q = t & 3;
    float4 s0 = {0.f, 0.f, 0.f, 0.f}, s1 = s0, s2 = s0, s3 = s0;
    int grow = base + row;
    if (grow < nvalid) {
        const int* gp = graph + (size_t)grow * MAXNB;
#pragma unroll 2
        for (int j = 0; j < MAXNB; j++) {
            int idx = gp[j];
            const float* p = (idx < M_N) ? (tree + (size_t)idx * H_N)
                                         : (src + (size_t)(idx - M_N) * H_N);
            const float4* p4 = (const float4*)(p + k0) + q * 4;
            float4 v0 = p4[0], v1 = p4[1], v2 = p4[2], v3 = p4[3];
            s0.x += v0.x; s0.y += v0.y; s0.z += v0.z; s0.w += v0.w;
            s1.x += v1.x; s1.y += v1.y; s1.z += v1.z; s1.w += v1.w;
            s2.x += v2.x; s2.y += v2.y; s2.z += v2.z; s2.w += v2.w;
            s3.x += v3.x; s3.y += v3.y; s3.z += v3.z; s3.w += v3.w;
        }
    }
    float4* out = (float4*)(sX + row * 64) + q * 4;
    out[0] = s0; out[1] = s1; out[2] = s2; out[3] = s3;
}

// ---------------------------------------------------------------------------
// binput = fbonds @ W_i ; g_gm0 = relu(binput)
// ---------------------------------------------------------------------------
__global__ __launch_bounds__(256, 2) void k_binput(const float* __restrict__ fbonds,
                                                   const float* __restrict__ Wi) {
    __shared__ __align__(16) float sW[FB * H_N];  // 20 KB
    __shared__ __align__(16) float sF[64 * FB];   // 10 KB
    int t = threadIdx.x;
    int tx = t & 31, wy = t >> 5;
    int b0 = blockIdx.x * 64;
    {
        const float4* src = (const float4*)Wi;
        float4* dst = (float4*)sW;
#pragma unroll
        for (int i = t; i < FB * H_N / 4; i += 256) dst[i] = src[i];
    }
    {
        const float4* src = (const float4*)(fbonds + (size_t)b0 * FB);
        float4* dst = (float4*)sF;
#pragma unroll
        for (int i = t; i < 64 * FB / 4; i += 256) dst[i] = src[i];
    }
    __syncthreads();
    float4 acc[8];
#pragma unroll
    for (int r = 0; r < 8; r++) acc[r] = make_float4(0.f, 0.f, 0.f, 0.f);
    gemm_tile64<FB / 4, FB / 4>(sW, sF, wy, tx, acc);
#pragma unroll
    for (int rr = 0; rr < 8; rr++) {
        size_t b = (size_t)(b0 + wy + rr * 8);
        ((float4*)g_binput)[b * 32 + tx] = acc[rr];
        float4 o = make_float4(fmaxf(acc[rr].x, 0.f), fmaxf(acc[rr].y, 0.f),
                               fmaxf(acc[rr].z, 0.f), fmaxf(acc[rr].w, 0.f));
        ((float4*)g_gm0)[b * 32 + tx] = o;
    }
}

// ---------------------------------------------------------------------------
// One message-passing iteration: dst = relu(binput + gather_sum(src) @ W_h)
// ---------------------------------------------------------------------------
__global__ __launch_bounds__(256, 2) void k_iter(const float* __restrict__ tree,
                                                  const int* __restrict__ bgraph,
                                                  const float* __restrict__ Wh,
                                                  int srcsel) {
    __shared__ __align__(16) float sW[64 * H_N];  // 32 KB
    __shared__ __align__(16) float sX[64 * 64];   // 16 KB  (total = 48 KB exactly)
    const float* src = srcsel ? g_gm1 : g_gm0;
    float* dst = srcsel ? g_gm0 : g_gm1;
    int t = threadIdx.x;
    int tx = t & 31, wy = t >> 5;
    int b0 = blockIdx.x * 64;
    float4 acc[8];
#pragma unroll
    for (int r = 0; r < 8; r++) acc[r] = make_float4(0.f, 0.f, 0.f, 0.f);

#pragma unroll
    for (int c = 0; c < 2; c++) {
        int k0 = c * 64;
        if (c) __syncthreads();
        {
            const float4* wsrc = (const float4*)(Wh + (size_t)k0 * H_N);
            float4* wdst = (float4*)sW;
#pragma unroll
            for (int i = 0; i < 8; i++) wdst[t + i * 256] = wsrc[t + i * 256];
        }
        gather64(sX, bgraph, tree, src, b0, k0, t, B_N);
        __syncthreads();
        gemm_tile64<16, 16>(sW, sX, wy, tx, acc);
    }
#pragma unroll
    for (int rr = 0; rr < 8; rr++) {
        size_t b = (size_t)(b0 + wy + rr * 8);
        float4 bi = ((const float4*)g_binput)[b * 32 + tx];
        float4 o = make_float4(fmaxf(acc[rr].x + bi.x, 0.f), fmaxf(acc[rr].y + bi.y, 0.f),
                               fmaxf(acc[rr].z + bi.z, 0.f), fmaxf(acc[rr].w + bi.w, 0.f));
        ((float4*)dst)[b * 32 + tx] = o;
    }
}

// ---------------------------------------------------------------------------
// Atom stage: ah = relu([fatoms, gather_sum(final msg via agraph)] @ W_o + b_o)
// K chunks: 36 (fatoms, padded) + 64 + 64. Final msg graph part in g_gm0.
// ---------------------------------------------------------------------------
__global__ __launch_bounds__(256, 2) void k_atom(const float* __restrict__ fatoms,
                                                  const float* __restrict__ tree,
                                                  const int* __restrict__ agraph,
                                                  const float* __restrict__ Wo,
                                                  const float* __restrict__ bo) {
    __shared__ __align__(16) float sW[64 * H_N];
    __shared__ __align__(16) float sX[64 * 64];
    int t = threadIdx.x;
    int tx = t & 31, wy = t >> 5;
    int a0 = blockIdx.x * 64;
    float4 bov = ((const float4*)bo)[tx];
    float4 acc[8];
#pragma unroll
    for (int r = 0; r < 8; r++) acc[r] = bov;  // bias folded in

    // chunk 0: fatoms columns (35 real + 1 zero pad -> 36, 9 gemm steps)
    {
        const float4* wsrc = (const float4*)Wo;
        float4* wdst = (float4*)sW;
        float4 z4 = make_float4(0.f, 0.f, 0.f, 0.f);
        for (int i = t; i < 36 * H_N / 4; i += 256)
            wdst[i] = (i < FA * H_N / 4) ? wsrc[i] : z4;  // zero pad row 35
        for (int i = t; i < 64 * 36; i += 256) {
            int r = i / 36;
            int c = i - r * 36;
            int a = a0 + r;
            sX[r * 64 + c] = (c < FA && a < A_N) ? fatoms[(size_t)a * FA + c] : 0.f;
        }
        __syncthreads();
        gemm_tile64<9, 16>(sW, sX, wy, tx, acc);
    }
    // chunks 1-2: gathered neighbor message columns
#pragma unroll
    for (int c = 0; c < 2; c++) {
        int k0 = c * 64;
        __syncthreads();
        {
            const float4* wsrc = (const float4*)(Wo + (size_t)(FA + k0) * H_N);
            float4* wdst = (float4*)sW;
#pragma unroll
            for (int i = 0; i < 8; i++) wdst[t + i * 256] = wsrc[t + i * 256];
        }
        gather64(sX, agraph, tree, g_gm0, a0, k0, t, A_N);
        __syncthreads();
        gemm_tile64<16, 16>(sW, sX, wy, tx, acc);
    }
#pragma unroll
    for (int rr = 0; rr < 8; rr++) {
        int a = a0 + wy + rr * 8;
        if (a < A_N) {
            float4 o = make_float4(fmaxf(acc[rr].x, 0.f), fmaxf(acc[rr].y, 0.f),
                                   fmaxf(acc[rr].z, 0.f), fmaxf(acc[rr].w, 0.f));
            ((float4*)g_ah)[(size_t)a * 32 + tx] = o;
        }
    }
}

// ---------------------------------------------------------------------------
// Segment mean: mol_id sorted -> block m binary-searches its [lo,hi) range.
// Deterministic (no fp32 atomics).
// ---------------------------------------------------------------------------
__global__ __launch_bounds__(128) void k_mol(const int* __restrict__ mol_id,
                                             float* __restrict__ out) {
    int m = blockIdx.x;
    int h = threadIdx.x;
    __shared__ int sb[2];
    if (h < 2) {
        int v = m + h;
        int lo = 0, hi = A_N;
        while (lo < hi) {
            int mid = (lo + hi) >> 1;
            if (mol_id[mid] < v) lo = mid + 1;
            else hi = mid;
        }
        sb[h] = lo;
    }
    __syncthreads();
    int lo = sb[0], hi = sb[1];
    float s = 0.f;
    for (int a = lo; a < hi; a++) s += g_ah[(size_t)a * H_N + h];
    out[(size_t)m * H_N + h] = s / fmaxf((float)(hi - lo), 1.f);
}

// ---------------------------------------------------------------------------
extern "C" void kernel_launch(void* const* d_in, const int* in_sizes, int n_in,
                              void* d_out, int out_size) {
    const float* fatoms = (const float*)d_in[0];
    const float* fbonds = (const float*)d_in[1];
    const float* tree   = (const float*)d_in[2];
    const int*   agraph = (const int*)d_in[3];
    const int*   bgraph = (const int*)d_in[4];
    const int*   mol_id = (const int*)d_in[5];
    const float* Wi     = (const float*)d_in[6];
    const float* Wh     = (const float*)d_in[7];
    const float* Wo     = (const float*)d_in[8];
    const float* bo     = (const float*)d_in[9];
    float* out = (float*)d_out;

    k_binput<<<B_N / 64, 256>>>(fbonds, Wi);
    k_iter<<<B_N / 64, 256>>>(tree, bgraph, Wh, 0);  // gm0 -> gm1
    k_iter<<<B_N / 64, 256>>>(tree, bgraph, Wh, 1);  // gm1 -> gm0
    k_iter<<<B_N / 64, 256>>>(tree, bgraph, Wh, 0);  // gm0 -> gm1
    k_iter<<<B_N / 64, 256>>>(tree, bgraph, Wh, 1);  // gm1 -> gm0 (final)
    k_atom<<<(A_N + 63) / 64, 256>>>(fatoms, tree, agraph, Wo, bo);
    k_mol<<<NMOL_N, 128>>>(mol_id, out);
}

// round 3
// speedup vs baseline: 1.4870x; 1.1303x over previous
#include <cuda_runtime.h>

#define A_N 100000
#define B_N 200000
#define M_N 50000
#define H_N 128
#define NMOL_N 4000
#define MAXNB 8
#define FA 35
#define FB 40

// Scratch (device globals — no allocations allowed)
__device__ __align__(128) float g_gm0[(size_t)B_N * H_N];
__device__ __align__(128) float g_gm1[(size_t)B_N * H_N];
__device__ __align__(128) float g_binput[(size_t)B_N * H_N];
__device__ __align__(128) float g_ah[(size_t)A_N * H_N];

// ---------------------------------------------------------------------------
// 64-row x 128-col tile GEMM over a K-chunk of NSTEPS*4 columns.
// tx = t&31 -> h columns tx*4.. ; wy = t>>5 -> rows {wy, wy+8, ..., wy+56}.
// sW: [NSTEPS*4][128] (k,h). sX: row-major, XS4 float4 per row.
// xv loads warp-broadcast; wv loads 512B contiguous -> conflict-free.
// ---------------------------------------------------------------------------
template <int NSTEPS, int XS4>
__device__ __forceinline__ void gemm_tile64(const float* sW, const float* sX,
                                            int wy, int tx, float4 acc[8]) {
    const float4* w4 = (const float4*)sW;
    const float4* x4 = (const float4*)sX;
#pragma unroll
    for (int k4 = 0; k4 < NSTEPS; k4++) {
        float4 wv[4];
#pragma unroll
        for (int kk = 0; kk < 4; kk++) wv[kk] = w4[(k4 * 4 + kk) * 32 + tx];
#pragma unroll
        for (int rr = 0; rr < 8; rr++) {
            float4 xv = x4[(wy + rr * 8) * XS4 + k4];
            acc[rr].x = fmaf(xv.x, wv[0].x, acc[rr].x);
            acc[rr].y = fmaf(xv.x, wv[0].y, acc[rr].y);
            acc[rr].z = fmaf(xv.x, wv[0].z, acc[rr].z);
            acc[rr].w = fmaf(xv.x, wv[0].w, acc[rr].w);
            acc[rr].x = fmaf(xv.y, wv[1].x, acc[rr].x);
            acc[rr].y = fmaf(xv.y, wv[1].y, acc[rr].y);
            acc[rr].z = fmaf(xv.y, wv[1].z, acc[rr].z);
            acc[rr].w = fmaf(xv.y, wv[1].w, acc[rr].w);
            acc[rr].x = fmaf(xv.z, wv[2].x, acc[rr].x);
            acc[rr].y = fmaf(xv.z, wv[2].y, acc[rr].y);
            acc[rr].z = fmaf(xv.z, wv[2].z, acc[rr].z);
            acc[rr].w = fmaf(xv.z, wv[2].w, acc[rr].w);
            acc[rr].x = fmaf(xv.w, wv[3].x, acc[rr].x);
            acc[rr].y = fmaf(xv.w, wv[3].y, acc[rr].y);
            acc[rr].z = fmaf(xv.w, wv[3].z, acc[rr].z);
            acc[rr].w = fmaf(xv.w, wv[3].w, acc[rr].w);
        }
    }
}

// ---------------------------------------------------------------------------
// Gather-sum of 8 neighbor rows (cols k0..k0+31) into sX[64][32].
// 4 threads/row, 8 cols each. Neighbor indices cached in regs by caller.
// Fully unrolled: 16 independent LDG.128 in flight per thread.
// ---------------------------------------------------------------------------
__device__ __forceinline__ void gather32(float* sX, const int idx[MAXNB],
                                         const float* __restrict__ tree,
                                         const float* __restrict__ src,
                                         int k0, int row, int q, bool valid) {
    float4 s0 = {0.f, 0.f, 0.f, 0.f}, s1 = s0;
    if (valid) {
#pragma unroll
        for (int j = 0; j < MAXNB; j++) {
            const float* p = (idx[j] < M_N) ? (tree + (size_t)idx[j] * H_N)
                                            : (src + (size_t)(idx[j] - M_N) * H_N);
            const float4* p4 = (const float4*)(p + k0) + q * 2;
            float4 v0 = p4[0], v1 = p4[1];
            s0.x += v0.x; s0.y += v0.y; s0.z += v0.z; s0.w += v0.w;
            s1.x += v1.x; s1.y += v1.y; s1.z += v1.z; s1.w += v1.w;
        }
    }
    float4* out = (float4*)(sX + row * 32) + q * 2;
    out[0] = s0; out[1] = s1;
}

// ---------------------------------------------------------------------------
// binput = fbonds @ W_i ; g_gm0 = relu(binput)
// ---------------------------------------------------------------------------
__global__ __launch_bounds__(256, 2) void k_binput(const float* __restrict__ fbonds,
                                                   const float* __restrict__ Wi) {
    __shared__ __align__(16) float sW[FB * H_N];  // 20 KB
    __shared__ __align__(16) float sF[64 * FB];   // 10 KB
    int t = threadIdx.x;
    int tx = t & 31, wy = t >> 5;
    int b0 = blockIdx.x * 64;
    {
        const float4* src = (const float4*)Wi;
        float4* dst = (float4*)sW;
#pragma unroll
        for (int i = t; i < FB * H_N / 4; i += 256) dst[i] = src[i];
    }
    {
        const float4* src = (const float4*)(fbonds + (size_t)b0 * FB);
        float4* dst = (float4*)sF;
#pragma unroll
        for (int i = t; i < 64 * FB / 4; i += 256) dst[i] = src[i];
    }
    __syncthreads();
    float4 acc[8];
#pragma unroll
    for (int r = 0; r < 8; r++) acc[r] = make_float4(0.f, 0.f, 0.f, 0.f);
    gemm_tile64<FB / 4, FB / 4>(sW, sF, wy, tx, acc);
#pragma unroll
    for (int rr = 0; rr < 8; rr++) {
        size_t b = (size_t)(b0 + wy + rr * 8);
        ((float4*)g_binput)[b * 32 + tx] = acc[rr];
        float4 o = make_float4(fmaxf(acc[rr].x, 0.f), fmaxf(acc[rr].y, 0.f),
                               fmaxf(acc[rr].z, 0.f), fmaxf(acc[rr].w, 0.f));
        ((float4*)g_gm0)[b * 32 + tx] = o;
    }
}

// ---------------------------------------------------------------------------
// One message-passing iteration: dst = relu(binput + gather_sum(src) @ W_h)
// 4 K-chunks of 32; neighbor indices cached in registers across chunks.
// ---------------------------------------------------------------------------
__global__ __launch_bounds__(256, 3) void k_iter(const float* __restrict__ tree,
                                                  const int* __restrict__ bgraph,
                                                  const float* __restrict__ Wh,
                                                  int srcsel) {
    __shared__ __align__(16) float sW[32 * H_N];  // 16 KB
    __shared__ __align__(16) float sX[64 * 32];   // 8 KB
    const float* src = srcsel ? g_gm1 : g_gm0;
    float* dst = srcsel ? g_gm0 : g_gm1;
    int t = threadIdx.x;
    int tx = t & 31, wy = t >> 5;
    int row = t >> 2, q = t & 3;
    int b0 = blockIdx.x * 64;

    // cache this thread's gather row indices (reused in all 4 chunks)
    int idx[MAXNB];
    {
        const int* gp = bgraph + (size_t)(b0 + row) * MAXNB;
#pragma unroll
        for (int j = 0; j < MAXNB; j++) idx[j] = gp[j];
    }

    float4 acc[8];
#pragma unroll
    for (int r = 0; r < 8; r++) acc[r] = make_float4(0.f, 0.f, 0.f, 0.f);

#pragma unroll
    for (int c = 0; c < 4; c++) {
        int k0 = c * 32;
        if (c) __syncthreads();
        {
            const float4* wsrc = (const float4*)(Wh + (size_t)k0 * H_N);
            float4* wdst = (float4*)sW;
#pragma unroll
            for (int i = 0; i < 4; i++) wdst[t + i * 256] = wsrc[t + i * 256];
        }
        gather32(sX, idx, tree, src, k0, row, q, true);
        __syncthreads();
        gemm_tile64<8, 8>(sW, sX, wy, tx, acc);
    }
#pragma unroll
    for (int rr = 0; rr < 8; rr++) {
        size_t b = (size_t)(b0 + wy + rr * 8);
        float4 bi = ((const float4*)g_binput)[b * 32 + tx];
        float4 o = make_float4(fmaxf(acc[rr].x + bi.x, 0.f), fmaxf(acc[rr].y + bi.y, 0.f),
                               fmaxf(acc[rr].z + bi.z, 0.f), fmaxf(acc[rr].w + bi.w, 0.f));
        ((float4*)dst)[b * 32 + tx] = o;
    }
}

// ---------------------------------------------------------------------------
// Atom stage: ah = relu([fatoms, gather_sum(final msg via agraph)] @ W_o + b_o)
// K chunks: 36 (fatoms, padded) + 4x32 gather. Final msg graph part in g_gm0.
// ---------------------------------------------------------------------------
__global__ __launch_bounds__(256, 3) void k_atom(const float* __restrict__ fatoms,
                                                  const float* __restrict__ tree,
                                                  const int* __restrict__ agraph,
                                                  const float* __restrict__ Wo,
                                                  const float* __restrict__ bo) {
    __shared__ __align__(16) float sW[36 * H_N];  // 18 KB
    __shared__ __align__(16) float sX[64 * 36];   // 9 KB
    int t = threadIdx.x;
    int tx = t & 31, wy = t >> 5;
    int row = t >> 2, q = t & 3;
    int a0 = blockIdx.x * 64;
    bool rvalid = (a0 + row) < A_N;

    int idx[MAXNB];
    {
        const int* gp = agraph + (size_t)(rvalid ? (a0 + row) : 0) * MAXNB;
#pragma unroll
        for (int j = 0; j < MAXNB; j++) idx[j] = gp[j];
    }

    float4 bov = ((const float4*)bo)[tx];
    float4 acc[8];
#pragma unroll
    for (int r = 0; r < 8; r++) acc[r] = bov;  // bias folded in

    // chunk 0: fatoms columns (35 real + 1 zero pad -> 36, 9 gemm steps)
    {
        const float4* wsrc = (const float4*)Wo;
        float4* wdst = (float4*)sW;
        float4 z4 = make_float4(0.f, 0.f, 0.f, 0.f);
#pragma unroll
        for (int i = t; i < 36 * H_N / 4; i += 256)
            wdst[i] = (i < FA * H_N / 4) ? wsrc[i] : z4;  // zero pad row 35
        for (int i = t; i < 64 * 36; i += 256) {
            int r = i / 36;
            int c = i - r * 36;
            int a = a0 + r;
            sX[r * 36 + c] = (c < FA && a < A_N) ? fatoms[(size_t)a * FA + c] : 0.f;
        }
        __syncthreads();
        gemm_tile64<9, 9>(sW, sX, wy, tx, acc);
    }
    // chunks 1-4: gathered neighbor message columns (32 each)
#pragma unroll
    for (int c = 0; c < 4; c++) {
        int k0 = c * 32;
        __syncthreads();
        {
            const float4* wsrc = (const float4*)(Wo + (size_t)(FA + k0) * H_N);
            float4* wdst = (float4*)sW;
#pragma unroll
            for (int i = 0; i < 4; i++) wdst[t + i * 256] = wsrc[t + i * 256];
        }
        gather32(sX, idx, tree, g_gm0, k0, row, q, rvalid);
        __syncthreads();
        gemm_tile64<8, 8>(sW, sX, wy, tx, acc);
    }
#pragma unroll
    for (int rr = 0; rr < 8; rr++) {
        int a = a0 + wy + rr * 8;
        if (a < A_N) {
            float4 o = make_float4(fmaxf(acc[rr].x, 0.f), fmaxf(acc[rr].y, 0.f),
                                   fmaxf(acc[rr].z, 0.f), fmaxf(acc[rr].w, 0.f));
            ((float4*)g_ah)[(size_t)a * 32 + tx] = o;
        }
    }
}

// ---------------------------------------------------------------------------
// Segment mean: mol_id sorted -> block m binary-searches its [lo,hi) range.
// Deterministic (no fp32 atomics).
// ---------------------------------------------------------------------------
__global__ __launch_bounds__(128) void k_mol(const int* __restrict__ mol_id,
                                             float* __restrict__ out) {
    int m = blockIdx.x;
    int h = threadIdx.x;
    __shared__ int sb[2];
    if (h < 2) {
        int v = m + h;
        int lo = 0, hi = A_N;
        while (lo < hi) {
            int mid = (lo + hi) >> 1;
            if (mol_id[mid] < v) lo = mid + 1;
            else hi = mid;
        }
        sb[h] = lo;
    }
    __syncthreads();
    int lo = sb[0], hi = sb[1];
    float s = 0.f;
    for (int a = lo; a < hi; a++) s += g_ah[(size_t)a * H_N + h];
    out[(size_t)m * H_N + h] = s / fmaxf((float)(hi - lo), 1.f);
}

// ---------------------------------------------------------------------------
extern "C" void kernel_launch(void* const* d_in, const int* in_sizes, int n_in,
                              void* d_out, int out_size) {
    const float* fatoms = (const float*)d_in[0];
    const float* fbonds = (const float*)d_in[1];
    const float* tree   = (const float*)d_in[2];
    const int*   agraph = (const int*)d_in[3];
    const int*   bgraph = (const int*)d_in[4];
    const int*   mol_id = (const int*)d_in[5];
    const float* Wi     = (const float*)d_in[6];
    const float* Wh     = (const float*)d_in[7];
    const float* Wo     = (const float*)d_in[8];
    const float* bo     = (const float*)d_in[9];
    float* out = (float*)d_out;

    k_binput<<<B_N / 64, 256>>>(fbonds, Wi);
    k_iter<<<B_N / 64, 256>>>(tree, bgraph, Wh, 0);  // gm0 -> gm1
    k_iter<<<B_N / 64, 256>>>(tree, bgraph, Wh, 1);  // gm1 -> gm0
    k_iter<<<B_N / 64, 256>>>(tree, bgraph, Wh, 0);  // gm0 -> gm1
    k_iter<<<B_N / 64, 256>>>(tree, bgraph, Wh, 1);  // gm1 -> gm0 (final)
    k_atom<<<(A_N + 63) / 64, 256>>>(fatoms, tree, agraph, Wo, bo);
    k_mol<<<NMOL_N, 128>>>(mol_id, out);
}